// round 9
// baseline (speedup 1.0000x reference)
#include <cuda_runtime.h>
#include <cuda_fp16.h>
#include <math.h>
#include <stdint.h>

// ---------------- problem constants ----------------
#define IMGS 8
#define CIN  1024
#define P    1024
#define KC   28
#define KTOT 1052
#define KPAD 1056          // 33 K-stages of 32
#define COUT 2048
#define NB   4

#define STGB  32768
#define SMEMB (3 * STGB)   // 3-stage ring, 96KB -> 2 CTAs/SM

// ---------------- scratch ----------------
__device__ float  g_ctx [IMGS * KC * P];
__device__ __align__(16) __half g_Wh[COUT * KPAD], g_Wl[COUT * KPAD];
__device__ __align__(16) __half g_Xh[IMGS * P * KPAD];
__device__ __align__(16) __half g_Sh[(size_t)IMGS * P * COUT], g_Sl[(size_t)IMGS * P * COUT];
__device__ float  g_ssum[IMGS * P];
__device__ float  g_corr[(size_t)NB * P * P];              // scaled corr, [b][t][s]
__device__ unsigned g_smaxu[NB * P], g_tmaxu[NB * P];      // monotonic float keys
__device__ float  g_isx[NB * P], g_itx[NB * P];

__device__ const int c_dy[28] = {-3,-2,-1,0,1,2,3, -3,-2,-1,0,1,2,3, -3,-2,-1,0,1,2,3, 0,0,0,0,0,0,0};
__device__ const int c_dx[28] = {-3,-2,-1,0,1,2,3,  0, 0, 0,0,0,0,0,  3, 2, 1,0,-1,-2,-3, -3,-2,-1,0,1,2,3};

__device__ __forceinline__ const float* img_ptr(const float* src, const float* tgt, int img) {
    return (img < 4) ? (src + (size_t)img * CIN * P) : (tgt + (size_t)(img - 4) * CIN * P);
}
__device__ __forceinline__ uint32_t smem_u32(const void* p) {
    uint32_t a;
    asm("{ .reg .u64 t; cvta.to.shared.u64 t, %1; cvt.u32.u64 %0, t; }" : "=r"(a) : "l"(p));
    return a;
}
__device__ __forceinline__ void cp16(uint32_t dst, const void* src) {
    asm volatile("cp.async.cg.shared.global [%0], [%1], 16;" :: "r"(dst), "l"(src) : "memory");
}
__device__ __forceinline__ void ldsm4(uint32_t r[4], uint32_t a) {
    asm volatile("ldmatrix.sync.aligned.m8n8.x4.shared.b16 {%0,%1,%2,%3}, [%4];"
        : "=r"(r[0]), "=r"(r[1]), "=r"(r[2]), "=r"(r[3]) : "r"(a));
}
__device__ __forceinline__ void mma16816(float c[4], const uint32_t a[4], const uint32_t b[2]) {
    asm volatile("mma.sync.aligned.m16n8k16.row.col.f32.f16.f16.f32 "
        "{%0,%1,%2,%3},{%4,%5,%6,%7},{%8,%9},{%0,%1,%2,%3};"
        : "+f"(c[0]), "+f"(c[1]), "+f"(c[2]), "+f"(c[3])
        : "r"(a[0]), "r"(a[1]), "r"(a[2]), "r"(a[3]), "r"(b[0]), "r"(b[1]));
}
__device__ __forceinline__ unsigned fkey(float v) {
    unsigned b = __float_as_uint(v);
    return (b & 0x80000000u) ? ~b : (b | 0x80000000u);
}
__device__ __forceinline__ float funkey(unsigned k) {
    unsigned b = (k & 0x80000000u) ? (k & 0x7FFFFFFFu) : ~k;
    return __uint_as_float(b);
}

// ---------------- one 128x128x32 stage of MMA from swizzled smem (2-term) ----------------
__device__ __forceinline__ void compute_stage(uint32_t bb, const uint32_t aoff[2],
                                              const uint32_t boff[4], float acc[2][8][4])
{
#pragma unroll
    for (int kk = 0; kk < 2; kk++) {
        uint32_t a_h[2][4];
#pragma unroll
        for (int i = 0; i < 2; i++) {
            uint32_t ua = (bb + aoff[i]) ^ (kk << 5);
            ldsm4(a_h[i], ua);
        }
#pragma unroll
        for (int jj = 0; jj < 4; jj++) {
            uint32_t ub = (bb + boff[jj]) ^ (kk << 5);
            uint32_t bh4[4], bl4[4];
            ldsm4(bh4, ub);
            ldsm4(bl4, ub ^ 64);
#pragma unroll
            for (int i = 0; i < 2; i++) {
                mma16816(acc[i][jj * 2],     a_h[i], bh4 + 0);
                mma16816(acc[i][jj * 2],     a_h[i], bl4 + 0);
                mma16816(acc[i][jj * 2 + 1], a_h[i], bh4 + 2);
                mma16816(acc[i][jj * 2 + 1], a_h[i], bl4 + 2);
            }
        }
    }
}

// ---------------- GEMM mainloop: 3-stage cp.async ring, 1 sync/stage, swizzled smem ----------------
__device__ __forceinline__ void gemm_ml(uint32_t smb,
    const __half* Ah, const __half* Bh, const __half* Bl,
    int lda, int ldb, int K, float acc[2][8][4])
{
    int tid = threadIdx.x, lane = tid & 31, wid = tid >> 5;
    int wm = wid & 3, wn = wid >> 2;
    int rr = tid >> 2, cc = tid & 3;
    uint32_t d0 = (uint32_t)rr * 128 + (uint32_t)((cc ^ (rr & 7)) * 16);
    const __half* pA0  = Ah + (size_t)rr * lda + cc * 8;
    const __half* pA1  = Ah + (size_t)(rr + 64) * lda + cc * 8;
    const __half* pB0  = Bh + (size_t)rr * ldb + cc * 8;
    const __half* pB1  = Bh + (size_t)(rr + 64) * ldb + cc * 8;
    const __half* pBl0 = Bl + (size_t)rr * ldb + cc * 8;
    const __half* pBl1 = Bl + (size_t)(rr + 64) * ldb + cc * 8;

    uint32_t aoff[2], boff[4];
#pragma unroll
    for (int i = 0; i < 2; i++) {
        int row = wm * 32 + i * 16 + (lane & 15);
        aoff[i] = (uint32_t)row * 128 + (uint32_t)((((lane >> 4) ^ (lane & 7)) & 7) * 16);
    }
#pragma unroll
    for (int jj = 0; jj < 4; jj++) {
        int row = 128 + wn * 64 + jj * 16 + (lane & 7) + ((lane >> 4) & 1) * 8;
        boff[jj] = (uint32_t)row * 128 + (uint32_t)(((((lane >> 3) & 1) ^ (lane & 7)) & 7) * 16);
    }

#define ISSUE(buf, k0) do { \
        uint32_t bb = smb + (uint32_t)(buf) * STGB; \
        cp16(bb + d0,                 pA0  + (k0)); \
        cp16(bb + d0 + 8192,          pA1  + (k0)); \
        cp16(bb + d0 + 16384,         pB0  + (k0)); \
        cp16((bb + d0 + 16384) ^ 64,  pBl0 + (k0)); \
        cp16(bb + d0 + 24576,         pB1  + (k0)); \
        cp16((bb + d0 + 24576) ^ 64,  pBl1 + (k0)); \
        asm volatile("cp.async.commit_group;" ::: "memory"); \
    } while (0)

    int nst = K / 32;
    ISSUE(0, 0);
    ISSUE(1, 32);
    int buf = 0;
    for (int s = 0; s < nst; s++) {
        if (s + 1 < nst) { asm volatile("cp.async.wait_group 1;" ::: "memory"); }
        else             { asm volatile("cp.async.wait_group 0;" ::: "memory"); }
        __syncthreads();
        int nx = s + 2;
        if (nx < nst) ISSUE(nx % 3, nx * 32);
        compute_stage(smb + (uint32_t)buf * STGB, aoff, boff, acc);
        buf = (buf + 1 == 3) ? 0 : buf + 1;
    }
#undef ISSUE
}

// ---------------- kernel 1: context channels with fused local norms ----------------
__global__ void k_ctx(const float* __restrict__ src, const float* __restrict__ tgt) {
    int img = blockIdx.x, y = blockIdx.y;
    const float* f = img_ptr(src, tgt, img);
    int lane = threadIdx.x & 31, w = threadIdx.x >> 5;
    __shared__ float tile[8][7][32];
    __shared__ float red[28][8][32];
    __shared__ float redn[7][8][32];
    __shared__ float invl[7][32];
    float acc[28];
    float accn[7];
#pragma unroll
    for (int k = 0; k < 28; k++) acc[k] = 0.f;
#pragma unroll
    for (int d = 0; d < 7; d++) accn[d] = 0.f;

    for (int c = w; c < CIN; c += 8) {
#pragma unroll
        for (int dy = 0; dy < 7; dy++) {
            int yy = y + dy - 3;
            float v = (yy >= 0 && yy < 32) ? f[c * P + yy * 32 + lane] : 0.f;
            tile[w][dy][lane] = v;
            accn[dy] = fmaf(v, v, accn[dy]);
        }
        __syncwarp();
        float v0 = tile[w][3][lane];
#pragma unroll
        for (int k = 0; k < 28; k++) {
            int xx = lane + c_dx[k];
            float v = (xx >= 0 && xx < 32) ? tile[w][c_dy[k] + 3][xx] : 0.f;
            acc[k] = fmaf(v0, v, acc[k]);
        }
        __syncwarp();
    }
#pragma unroll
    for (int k = 0; k < 28; k++) red[k][w][lane] = acc[k];
#pragma unroll
    for (int d = 0; d < 7; d++) redn[d][w][lane] = accn[d];
    __syncthreads();

    if (threadIdx.x < 7 * 32) {
        int d = threadIdx.x >> 5, x = threadIdx.x & 31;
        float s = 0.f;
#pragma unroll
        for (int i = 0; i < 8; i++) s += redn[d][i][x];
        invl[d][x] = 1.f / fmaxf(sqrtf(s), 1e-12f);
    }
    __syncthreads();

    for (int idx = threadIdx.x; idx < 28 * 32; idx += 256) {
        int k = idx >> 5, x = idx & 31;
        float s = 0.f;
#pragma unroll
        for (int i = 0; i < 8; i++) s += red[k][i][x];
        int yy = y + c_dy[k], xx = x + c_dx[k];
        float o = 0.f;
        if (yy >= 0 && yy < 32 && xx >= 0 && xx < 32)
            o = s * invl[3][x] * invl[c_dy[k] + 3][xx];
        g_ctx[((size_t)img * KC + k) * P + y * 32 + x] = o;
    }
}

// ---------------- kernel 2: transpose inputs (z<8) / pad+split W + zero scratch (z==8) ----------------
__global__ void k_xtw(const float* __restrict__ src, const float* __restrict__ tgt,
                      const float* __restrict__ W) {
    int img = blockIdx.z;
    int tid = threadIdx.y * 32 + threadIdx.x;
    if (img == 8) {
        int gid = (blockIdx.y * 33 + blockIdx.x) * 256 + tid;
        if (gid < IMGS * P) g_ssum[gid] = 0.f;
        if (gid < NB * P) { g_smaxu[gid] = 0u; g_tmaxu[gid] = 0u; }
        size_t base = ((size_t)gid) * 8;
#pragma unroll
        for (int u = 0; u < 8; u++) {
            size_t idx = base + u;
            int o = (int)(idx / KPAD);
            int k = (int)(idx - (size_t)o * KPAD);
            float v = (k < KTOT) ? W[(size_t)o * KTOT + k] : 0.f;
            __half h = __float2half_rn(v);
            g_Wh[idx] = h;
            g_Wl[idx] = __float2half_rn(v - __half2float(h));
        }
        return;
    }
    int cblk = blockIdx.x, pblk = blockIdx.y;
    const float* f = img_ptr(src, tgt, img);
    __shared__ float tile[32][33];
    int tx = threadIdx.x;
    for (int r = threadIdx.y; r < 32; r += 8) {
        int c = cblk * 32 + r, p = pblk * 32 + tx;
        float v = 0.f;
        if (c < CIN) v = f[(size_t)c * P + p];
        else if (c < KTOT) v = g_ctx[((size_t)img * KC + (c - CIN)) * P + p];
        tile[r][tx] = v;
    }
    __syncthreads();
    for (int r = threadIdx.y; r < 32; r += 8) {
        int p = pblk * 32 + r, c = cblk * 32 + tx;
        g_Xh[((size_t)img * P + p) * KPAD + c] = __float2half_rn(tile[tx][r]);
    }
}

// ---------------- conv GEMM (persistent, 2-term: Xh*(Wh+Wl)) ----------------
__global__ void __launch_bounds__(256, 2) k_conv(const float* __restrict__ bias) {
    extern __shared__ char smc[];
    __shared__ float sss[128];
    uint32_t smb = (smem_u32(smc) + 127u) & ~127u;
    int lane = threadIdx.x & 31, wid = threadIdx.x >> 5, wm = wid & 3, wn = wid >> 2;

    for (int t = blockIdx.x; t < 1024; t += gridDim.x) {
        int img = t >> 7, r = t & 127;
        int bm = (r >> 4) * 128, bn = (r & 15) * 128;   // bm: p, bn: o
        const __half* Ah = g_Xh + ((size_t)img * P + bm) * KPAD;
        const __half* Bh = g_Wh + (size_t)bn * KPAD;
        const __half* Bl = g_Wl + (size_t)bn * KPAD;
        float acc[2][8][4] = {};
        gemm_ml(smb, Ah, Bh, Bl, KPAD, KPAD, KPAD, acc);

        if (threadIdx.x < 128) sss[threadIdx.x] = 0.f;
        __syncthreads();

        bool needLo = (img >= 4);
        __half* Shp = g_Sh + (size_t)img * P * COUT;
        __half* Slp = g_Sl + (size_t)img * P * COUT;
#pragma unroll
        for (int i = 0; i < 2; i++) {
            int pl0 = wm * 32 + i * 16 + (lane >> 2);
            int p0 = bm + pl0;
            float q0 = 0.f, q1 = 0.f;
#pragma unroll
            for (int j = 0; j < 8; j++) {
                int o = bn + wn * 64 + j * 8 + 2 * (lane & 3);
                float2 bb = *(const float2*)(bias + o);
                float a0 = fmaxf(acc[i][j][0] + bb.x, 0.f);
                float a1 = fmaxf(acc[i][j][1] + bb.y, 0.f);
                float a2 = fmaxf(acc[i][j][2] + bb.x, 0.f);
                float a3 = fmaxf(acc[i][j][3] + bb.y, 0.f);
                q0 = fmaf(a0, a0, fmaf(a1, a1, q0));
                q1 = fmaf(a2, a2, fmaf(a3, a3, q1));
                __half h0 = __float2half_rn(a0), h1 = __float2half_rn(a1);
                __half h2 = __float2half_rn(a2), h3 = __float2half_rn(a3);
                *(__half2*)(Shp + (size_t)p0 * COUT + o)       = __halves2half2(h0, h1);
                *(__half2*)(Shp + (size_t)(p0 + 8) * COUT + o) = __halves2half2(h2, h3);
                if (needLo) {
                    *(__half2*)(Slp + (size_t)p0 * COUT + o)       =
                        __halves2half2(__float2half_rn(a0 - __half2float(h0)), __float2half_rn(a1 - __half2float(h1)));
                    *(__half2*)(Slp + (size_t)(p0 + 8) * COUT + o) =
                        __halves2half2(__float2half_rn(a2 - __half2float(h2)), __float2half_rn(a3 - __half2float(h3)));
                }
            }
            atomicAdd(&sss[pl0], q0);
            atomicAdd(&sss[pl0 + 8], q1);
        }
        __syncthreads();
        if (threadIdx.x < 128) atomicAdd(&g_ssum[img * P + bm + threadIdx.x], sss[threadIdx.x]);
        __syncthreads();
    }
}

// ---------------- corr GEMM (2-term): scaled corr [b][t][s] + fused tile maxes ----------------
__global__ void __launch_bounds__(256, 2) k_corr() {
    extern __shared__ char smc[];
    __shared__ unsigned su[128], tu[128];
    uint32_t smb = (smem_u32(smc) + 127u) & ~127u;
    int b = blockIdx.z, bm = blockIdx.y * 128, bn = blockIdx.x * 128;  // bm: s, bn: t
    const __half* Ah = g_Sh + ((size_t)b * P + bm) * COUT;
    const __half* Bh = g_Sh + ((size_t)(4 + b) * P + bn) * COUT;
    const __half* Bl = g_Sl + ((size_t)(4 + b) * P + bn) * COUT;
    float acc[2][8][4] = {};
    gemm_ml(smb, Ah, Bh, Bl, COUT, COUT, COUT, acc);

    if (threadIdx.x < 128) { su[threadIdx.x] = 0u; tu[threadIdx.x] = 0u; }
    __syncthreads();

    int lane = threadIdx.x & 31, wid = threadIdx.x >> 5, wm = wid & 3, wn = wid >> 2;
    const float* ssums = g_ssum + b * P;
    const float* ssumt = g_ssum + (4 + b) * P;
    float* C = g_corr + (size_t)b * P * P;
#pragma unroll
    for (int i = 0; i < 2; i++) {
        int sl0 = wm * 32 + i * 16 + (lane >> 2);
        int s0 = bm + sl0;
        float is0 = rsqrtf(ssums[s0] + 1e-6f), is1 = rsqrtf(ssums[s0 + 8] + 1e-6f);
        unsigned ks0 = 0u, ks1 = 0u;
#pragma unroll
        for (int j = 0; j < 8; j++) {
            int tl0 = wn * 64 + j * 8 + 2 * (lane & 3);
            int t0 = bn + tl0;
            float it0 = rsqrtf(ssumt[t0] + 1e-6f), it1 = rsqrtf(ssumt[t0 + 1] + 1e-6f);
            float c00 = acc[i][j][0] * is0 * it0;
            float c01 = acc[i][j][1] * is0 * it1;
            float c10 = acc[i][j][2] * is1 * it0;
            float c11 = acc[i][j][3] * is1 * it1;
            C[(size_t)t0 * P + s0]           = c00;
            C[(size_t)(t0 + 1) * P + s0]     = c01;
            C[(size_t)t0 * P + s0 + 8]       = c10;
            C[(size_t)(t0 + 1) * P + s0 + 8] = c11;
            unsigned k00 = fkey(c00), k01 = fkey(c01), k10 = fkey(c10), k11 = fkey(c11);
            ks0 = max(ks0, max(k00, k01));
            ks1 = max(ks1, max(k10, k11));
            atomicMax(&tu[tl0],     max(k00, k10));
            atomicMax(&tu[tl0 + 1], max(k01, k11));
        }
        atomicMax(&su[sl0], ks0);
        atomicMax(&su[sl0 + 8], ks1);
    }
    __syncthreads();
    if (threadIdx.x < 128) {
        atomicMax(&g_smaxu[b * P + bm + threadIdx.x], su[threadIdx.x]);
        atomicMax(&g_tmaxu[b * P + bn + threadIdx.x], tu[threadIdx.x]);
    }
}

// ---------------- keys -> guarded reciprocals ----------------
__global__ void k_recip() {
    int i = blockIdx.x * 256 + threadIdx.x;
    if (i < NB * P) {
        float v = funkey(g_smaxu[i]); if (v == 0.f) v = 1e-30f;
        g_isx[i] = 1.f / v;
        float w = funkey(g_tmaxu[i]); if (w == 0.f) w = 1e-30f;
        g_itx[i] = 1.f / w;
    }
}

// ---------------- fused filter + resize + softmax + soft-argmax + flow ----------------
__global__ void __launch_bounds__(256) k_flow(float* __restrict__ out) {
    int tx = blockIdx.x, ty = blockIdx.y, b = blockIdx.z;
    int tid = threadIdx.x;
    const float sc = 31.f / 63.f;
    float fy = ty * sc; int y0 = (int)fy; int y1 = min(y0 + 1, 31); float wy = fy - (float)y0;
    float fx = tx * sc; int x0 = (int)fx; int x1 = min(x0 + 1, 31); float wx = fx - (float)x0;
    int t00 = y0 * 32 + x0, t01 = y0 * 32 + x1, t10 = y1 * 32 + x0, t11 = y1 * 32 + x1;
    const float* C = g_corr + (size_t)b * P * P;
    const float* r00 = C + (size_t)t00 * P;
    const float* r01 = C + (size_t)t01 * P;
    const float* r10 = C + (size_t)t10 * P;
    const float* r11 = C + (size_t)t11 * P;
    float ww00 = (1.f - wy) * (1.f - wx) * g_itx[b * P + t00];
    float ww01 = (1.f - wy) * wx         * g_itx[b * P + t01];
    float ww10 = wy * (1.f - wx)         * g_itx[b * P + t10];
    float ww11 = wy * wx                 * g_itx[b * P + t11];
    const float* isx = g_isx + b * P;
    __shared__ float m[P];
    for (int s = tid; s < P; s += 256) {
        float v00 = r00[s], v01 = r01[s], v10 = r10[s], v11 = r11[s];
        float a = ww00 * v00 * v00 * v00 + ww01 * v01 * v01 * v01
                + ww10 * v10 * v10 * v10 + ww11 * v11 * v11 * v11;
        m[s] = a * isx[s];
    }
    __syncthreads();
    float mx = -INFINITY;
    for (int s = tid; s < P; s += 256) mx = fmaxf(mx, m[s]);
    __shared__ float rd[8];
#pragma unroll
    for (int o = 16; o > 0; o >>= 1) mx = fmaxf(mx, __shfl_xor_sync(0xffffffffu, mx, o));
    if ((tid & 31) == 0) rd[tid >> 5] = mx;
    __syncthreads();
    float M = -INFINITY;
#pragma unroll
    for (int i = 0; i < 8; i++) M = fmaxf(M, rd[i]);
    float sum = 0.f, sx = 0.f, sy = 0.f;
    for (int s = tid; s < 4096; s += 256) {
        int i = s >> 6, j = s & 63;
        float gy = i * sc; int yy0 = (int)gy; int yy1 = min(yy0 + 1, 31); float a = gy - (float)yy0;
        float gx = j * sc; int xx0 = (int)gx; int xx1 = min(xx0 + 1, 31); float bq = gx - (float)xx0;
        float v = (1.f - a) * ((1.f - bq) * m[yy0 * 32 + xx0] + bq * m[yy0 * 32 + xx1])
                +        a  * ((1.f - bq) * m[yy1 * 32 + xx0] + bq * m[yy1 * 32 + xx1]);
        float e = __expf((v - M) * 50.f);
        sum += e;
        sx = fmaf(e, -1.f + j * (2.f / 63.f), sx);
        sy = fmaf(e, -1.f + i * (2.f / 63.f), sy);
    }
    __shared__ float rs[8], rx[8], ry[8];
#pragma unroll
    for (int o = 16; o > 0; o >>= 1) {
        sum += __shfl_xor_sync(0xffffffffu, sum, o);
        sx  += __shfl_xor_sync(0xffffffffu, sx,  o);
        sy  += __shfl_xor_sync(0xffffffffu, sy,  o);
    }
    if ((tid & 31) == 0) { rs[tid >> 5] = sum; rx[tid >> 5] = sx; ry[tid >> 5] = sy; }
    __syncthreads();
    if (tid == 0) {
        float S = 0.f, X = 0.f, Y = 0.f;
#pragma unroll
        for (int i = 0; i < 8; i++) { S += rs[i]; X += rx[i]; Y += ry[i]; }
        float gx_ = X / S, gy_ = Y / S;
        out[(size_t)b * 8192 + (size_t)ty * 64 + tx]        = (gx_ + 1.f) * 31.5f - (float)tx;
        out[(size_t)b * 8192 + 4096 + (size_t)ty * 64 + tx] = (gy_ + 1.f) * 31.5f - (float)ty;
    }
}

// ---------------- launch ----------------
extern "C" void kernel_launch(void* const* d_in, const int* in_sizes, int n_in,
                              void* d_out, int out_size) {
    const float* src  = (const float*)d_in[0];
    const float* tgt  = (const float*)d_in[1];
    const float* W    = (const float*)d_in[2];
    const float* bias = (const float*)d_in[3];
    float* out = (float*)d_out;

    cudaFuncSetAttribute(k_conv, cudaFuncAttributeMaxDynamicSharedMemorySize, SMEMB);
    cudaFuncSetAttribute(k_corr, cudaFuncAttributeMaxDynamicSharedMemorySize, SMEMB);

    k_ctx  <<<dim3(8, 32), 256>>>(src, tgt);
    k_xtw  <<<dim3(33, 32, 9), dim3(32, 8)>>>(src, tgt, W);
    k_conv <<<296, 256, SMEMB>>>(bias);
    k_corr <<<dim3(8, 8, 4), 256, SMEMB>>>();
    k_recip<<<16, 256>>>();
    k_flow <<<dim3(64, 64, 4), 256>>>(out);
}

// round 10
// speedup vs baseline: 1.0087x; 1.0087x over previous
#include <cuda_runtime.h>
#include <cuda_fp16.h>
#include <math.h>
#include <stdint.h>

// ---------------- problem constants ----------------
#define IMGS 8
#define CIN  1024
#define P    1024
#define KC   28
#define KTOT 1052
#define KPAD 1056          // 33 K-stages of 32
#define COUT 2048
#define NB   4

#define STGB  32768
#define SMEMB (3 * STGB)   // 3-stage ring, 96KB -> 2 CTAs/SM

// ---------------- scratch ----------------
__device__ float  g_ctx [IMGS * KC * P];
__device__ __align__(16) __half g_Wh[COUT * KPAD], g_Wl[COUT * KPAD];
__device__ __align__(16) __half g_Xh[IMGS * P * KPAD];
__device__ __align__(16) __half g_Sh[(size_t)IMGS * P * COUT], g_Sl[(size_t)IMGS * P * COUT];
__device__ float  g_ssum[IMGS * P];
__device__ float  g_corr[(size_t)NB * P * P];              // scaled corr, [b][t][s]
__device__ unsigned g_smaxu[NB * P], g_tmaxu[NB * P];      // monotonic float keys
__device__ float  g_isx[NB * P], g_itx[NB * P];

__device__ const int c_dy[28] = {-3,-2,-1,0,1,2,3, -3,-2,-1,0,1,2,3, -3,-2,-1,0,1,2,3, 0,0,0,0,0,0,0};
__device__ const int c_dx[28] = {-3,-2,-1,0,1,2,3,  0, 0, 0,0,0,0,0,  3, 2, 1,0,-1,-2,-3, -3,-2,-1,0,1,2,3};

__device__ __forceinline__ const float* img_ptr(const float* src, const float* tgt, int img) {
    return (img < 4) ? (src + (size_t)img * CIN * P) : (tgt + (size_t)(img - 4) * CIN * P);
}
__device__ __forceinline__ uint32_t smem_u32(const void* p) {
    uint32_t a;
    asm("{ .reg .u64 t; cvta.to.shared.u64 t, %1; cvt.u32.u64 %0, t; }" : "=r"(a) : "l"(p));
    return a;
}
__device__ __forceinline__ void cp16(uint32_t dst, const void* src) {
    asm volatile("cp.async.cg.shared.global [%0], [%1], 16;" :: "r"(dst), "l"(src) : "memory");
}
__device__ __forceinline__ void ldsm4(uint32_t r[4], uint32_t a) {
    asm volatile("ldmatrix.sync.aligned.m8n8.x4.shared.b16 {%0,%1,%2,%3}, [%4];"
        : "=r"(r[0]), "=r"(r[1]), "=r"(r[2]), "=r"(r[3]) : "r"(a));
}
__device__ __forceinline__ void mma16816(float c[4], const uint32_t a[4], const uint32_t b[2]) {
    asm volatile("mma.sync.aligned.m16n8k16.row.col.f32.f16.f16.f32 "
        "{%0,%1,%2,%3},{%4,%5,%6,%7},{%8,%9},{%0,%1,%2,%3};"
        : "+f"(c[0]), "+f"(c[1]), "+f"(c[2]), "+f"(c[3])
        : "r"(a[0]), "r"(a[1]), "r"(a[2]), "r"(a[3]), "r"(b[0]), "r"(b[1]));
}
__device__ __forceinline__ unsigned fkey(float v) {
    unsigned b = __float_as_uint(v);
    return (b & 0x80000000u) ? ~b : (b | 0x80000000u);
}
__device__ __forceinline__ float funkey(unsigned k) {
    unsigned b = (k & 0x80000000u) ? (k & 0x7FFFFFFFu) : ~k;
    return __uint_as_float(b);
}

// ---------------- one 128x128x32 stage of MMA from swizzled smem (2-term) ----------------
__device__ __forceinline__ void compute_stage(uint32_t bb, const uint32_t aoff[2],
                                              const uint32_t boff[4], float acc[2][8][4])
{
#pragma unroll
    for (int kk = 0; kk < 2; kk++) {
        uint32_t a_h[2][4];
#pragma unroll
        for (int i = 0; i < 2; i++) {
            uint32_t ua = (bb + aoff[i]) ^ (kk << 5);
            ldsm4(a_h[i], ua);
        }
#pragma unroll
        for (int jj = 0; jj < 4; jj++) {
            uint32_t ub = (bb + boff[jj]) ^ (kk << 5);
            uint32_t bh4[4], bl4[4];
            ldsm4(bh4, ub);
            ldsm4(bl4, ub ^ 64);
#pragma unroll
            for (int i = 0; i < 2; i++) {
                mma16816(acc[i][jj * 2],     a_h[i], bh4 + 0);
                mma16816(acc[i][jj * 2],     a_h[i], bl4 + 0);
                mma16816(acc[i][jj * 2 + 1], a_h[i], bh4 + 2);
                mma16816(acc[i][jj * 2 + 1], a_h[i], bl4 + 2);
            }
        }
    }
}

// ---------------- GEMM mainloop: 3-stage cp.async ring, 1 sync/stage, swizzled smem ----------------
__device__ __forceinline__ void gemm_ml(uint32_t smb,
    const __half* Ah, const __half* Bh, const __half* Bl,
    int lda, int ldb, int K, float acc[2][8][4])
{
    int tid = threadIdx.x, lane = tid & 31, wid = tid >> 5;
    int wm = wid & 3, wn = wid >> 2;
    int rr = tid >> 2, cc = tid & 3;
    uint32_t d0 = (uint32_t)rr * 128 + (uint32_t)((cc ^ (rr & 7)) * 16);
    const __half* pA0  = Ah + (size_t)rr * lda + cc * 8;
    const __half* pA1  = Ah + (size_t)(rr + 64) * lda + cc * 8;
    const __half* pB0  = Bh + (size_t)rr * ldb + cc * 8;
    const __half* pB1  = Bh + (size_t)(rr + 64) * ldb + cc * 8;
    const __half* pBl0 = Bl + (size_t)rr * ldb + cc * 8;
    const __half* pBl1 = Bl + (size_t)(rr + 64) * ldb + cc * 8;

    uint32_t aoff[2], boff[4];
#pragma unroll
    for (int i = 0; i < 2; i++) {
        int row = wm * 32 + i * 16 + (lane & 15);
        aoff[i] = (uint32_t)row * 128 + (uint32_t)((((lane >> 4) ^ (lane & 7)) & 7) * 16);
    }
#pragma unroll
    for (int jj = 0; jj < 4; jj++) {
        int row = 128 + wn * 64 + jj * 16 + (lane & 7) + ((lane >> 4) & 1) * 8;
        boff[jj] = (uint32_t)row * 128 + (uint32_t)(((((lane >> 3) & 1) ^ (lane & 7)) & 7) * 16);
    }

#define ISSUE(buf, k0) do { \
        uint32_t bb = smb + (uint32_t)(buf) * STGB; \
        cp16(bb + d0,                 pA0  + (k0)); \
        cp16(bb + d0 + 8192,          pA1  + (k0)); \
        cp16(bb + d0 + 16384,         pB0  + (k0)); \
        cp16((bb + d0 + 16384) ^ 64,  pBl0 + (k0)); \
        cp16(bb + d0 + 24576,         pB1  + (k0)); \
        cp16((bb + d0 + 24576) ^ 64,  pBl1 + (k0)); \
        asm volatile("cp.async.commit_group;" ::: "memory"); \
    } while (0)

    int nst = K / 32;
    ISSUE(0, 0);
    ISSUE(1, 32);
    int buf = 0;
    for (int s = 0; s < nst; s++) {
        if (s + 1 < nst) { asm volatile("cp.async.wait_group 1;" ::: "memory"); }
        else             { asm volatile("cp.async.wait_group 0;" ::: "memory"); }
        __syncthreads();
        int nx = s + 2;
        if (nx < nst) ISSUE(nx % 3, nx * 32);
        compute_stage(smb + (uint32_t)buf * STGB, aoff, boff, acc);
        buf = (buf + 1 == 3) ? 0 : buf + 1;
    }
#undef ISSUE
}

// ---------------- kernel 1: context channels with fused local norms ----------------
__global__ void k_ctx(const float* __restrict__ src, const float* __restrict__ tgt) {
    int img = blockIdx.x, y = blockIdx.y;
    const float* f = img_ptr(src, tgt, img);
    int lane = threadIdx.x & 31, w = threadIdx.x >> 5;
    __shared__ float tile[8][7][32];
    __shared__ float red[28][8][32];
    __shared__ float redn[7][8][32];
    __shared__ float invl[7][32];
    float acc[28];
    float accn[7];
#pragma unroll
    for (int k = 0; k < 28; k++) acc[k] = 0.f;
#pragma unroll
    for (int d = 0; d < 7; d++) accn[d] = 0.f;

    for (int c = w; c < CIN; c += 8) {
#pragma unroll
        for (int dy = 0; dy < 7; dy++) {
            int yy = y + dy - 3;
            float v = (yy >= 0 && yy < 32) ? f[c * P + yy * 32 + lane] : 0.f;
            tile[w][dy][lane] = v;
            accn[dy] = fmaf(v, v, accn[dy]);
        }
        __syncwarp();
        float v0 = tile[w][3][lane];
#pragma unroll
        for (int k = 0; k < 28; k++) {
            int xx = lane + c_dx[k];
            float v = (xx >= 0 && xx < 32) ? tile[w][c_dy[k] + 3][xx] : 0.f;
            acc[k] = fmaf(v0, v, acc[k]);
        }
        __syncwarp();
    }
#pragma unroll
    for (int k = 0; k < 28; k++) red[k][w][lane] = acc[k];
#pragma unroll
    for (int d = 0; d < 7; d++) redn[d][w][lane] = accn[d];
    __syncthreads();

    if (threadIdx.x < 7 * 32) {
        int d = threadIdx.x >> 5, x = threadIdx.x & 31;
        float s = 0.f;
#pragma unroll
        for (int i = 0; i < 8; i++) s += redn[d][i][x];
        invl[d][x] = 1.f / fmaxf(sqrtf(s), 1e-12f);
    }
    __syncthreads();

    for (int idx = threadIdx.x; idx < 28 * 32; idx += 256) {
        int k = idx >> 5, x = idx & 31;
        float s = 0.f;
#pragma unroll
        for (int i = 0; i < 8; i++) s += red[k][i][x];
        int yy = y + c_dy[k], xx = x + c_dx[k];
        float o = 0.f;
        if (yy >= 0 && yy < 32 && xx >= 0 && xx < 32)
            o = s * invl[3][x] * invl[c_dy[k] + 3][xx];
        g_ctx[((size_t)img * KC + k) * P + y * 32 + x] = o;
    }
}

// ---------------- kernel 2: transpose inputs (z<8) / pad+split W + zero scratch (z==8) ----------------
__global__ void k_xtw(const float* __restrict__ src, const float* __restrict__ tgt,
                      const float* __restrict__ W) {
    int img = blockIdx.z;
    int tid = threadIdx.y * 32 + threadIdx.x;
    if (img == 8) {
        int gid = (blockIdx.y * 33 + blockIdx.x) * 256 + tid;
        if (gid < IMGS * P) g_ssum[gid] = 0.f;
        if (gid < NB * P) { g_smaxu[gid] = 0u; g_tmaxu[gid] = 0u; }
        size_t base = ((size_t)gid) * 8;
#pragma unroll
        for (int u = 0; u < 8; u++) {
            size_t idx = base + u;
            int o = (int)(idx / KPAD);
            int k = (int)(idx - (size_t)o * KPAD);
            float v = (k < KTOT) ? W[(size_t)o * KTOT + k] : 0.f;
            __half h = __float2half_rn(v);
            g_Wh[idx] = h;
            g_Wl[idx] = __float2half_rn(v - __half2float(h));
        }
        return;
    }
    int cblk = blockIdx.x, pblk = blockIdx.y;
    const float* f = img_ptr(src, tgt, img);
    __shared__ float tile[32][33];
    int tx = threadIdx.x;
    for (int r = threadIdx.y; r < 32; r += 8) {
        int c = cblk * 32 + r, p = pblk * 32 + tx;
        float v = 0.f;
        if (c < CIN) v = f[(size_t)c * P + p];
        else if (c < KTOT) v = g_ctx[((size_t)img * KC + (c - CIN)) * P + p];
        tile[r][tx] = v;
    }
    __syncthreads();
    for (int r = threadIdx.y; r < 32; r += 8) {
        int p = pblk * 32 + r, c = cblk * 32 + tx;
        g_Xh[((size_t)img * P + p) * KPAD + c] = __float2half_rn(tile[tx][r]);
    }
}

// ---------------- conv GEMM (non-persistent, 2-term: Xh*(Wh+Wl)) ----------------
__global__ void __launch_bounds__(256, 2) k_conv(const float* __restrict__ bias) {
    extern __shared__ char smc[];
    __shared__ float sss[128];
    uint32_t smb = (smem_u32(smc) + 127u) & ~127u;
    int img = blockIdx.z, bm = blockIdx.y * 128, bn = blockIdx.x * 128;  // bm: p, bn: o
    const __half* Ah = g_Xh + ((size_t)img * P + bm) * KPAD;
    const __half* Bh = g_Wh + (size_t)bn * KPAD;
    const __half* Bl = g_Wl + (size_t)bn * KPAD;
    float acc[2][8][4] = {};
    gemm_ml(smb, Ah, Bh, Bl, KPAD, KPAD, KPAD, acc);

    if (threadIdx.x < 128) sss[threadIdx.x] = 0.f;
    __syncthreads();

    int lane = threadIdx.x & 31, wid = threadIdx.x >> 5, wm = wid & 3, wn = wid >> 2;
    bool needLo = (img >= 4);
    __half* Shp = g_Sh + (size_t)img * P * COUT;
    __half* Slp = g_Sl + (size_t)img * P * COUT;
#pragma unroll
    for (int i = 0; i < 2; i++) {
        int pl0 = wm * 32 + i * 16 + (lane >> 2);
        int p0 = bm + pl0;
        float q0 = 0.f, q1 = 0.f;
#pragma unroll
        for (int j = 0; j < 8; j++) {
            int o = bn + wn * 64 + j * 8 + 2 * (lane & 3);
            float2 bb = *(const float2*)(bias + o);
            float a0 = fmaxf(acc[i][j][0] + bb.x, 0.f);
            float a1 = fmaxf(acc[i][j][1] + bb.y, 0.f);
            float a2 = fmaxf(acc[i][j][2] + bb.x, 0.f);
            float a3 = fmaxf(acc[i][j][3] + bb.y, 0.f);
            q0 = fmaf(a0, a0, fmaf(a1, a1, q0));
            q1 = fmaf(a2, a2, fmaf(a3, a3, q1));
            __half h0 = __float2half_rn(a0), h1 = __float2half_rn(a1);
            __half h2 = __float2half_rn(a2), h3 = __float2half_rn(a3);
            *(__half2*)(Shp + (size_t)p0 * COUT + o)       = __halves2half2(h0, h1);
            *(__half2*)(Shp + (size_t)(p0 + 8) * COUT + o) = __halves2half2(h2, h3);
            if (needLo) {
                *(__half2*)(Slp + (size_t)p0 * COUT + o)       =
                    __halves2half2(__float2half_rn(a0 - __half2float(h0)), __float2half_rn(a1 - __half2float(h1)));
                *(__half2*)(Slp + (size_t)(p0 + 8) * COUT + o) =
                    __halves2half2(__float2half_rn(a2 - __half2float(h2)), __float2half_rn(a3 - __half2float(h3)));
            }
        }
        atomicAdd(&sss[pl0], q0);
        atomicAdd(&sss[pl0 + 8], q1);
    }
    __syncthreads();
    if (threadIdx.x < 128) atomicAdd(&g_ssum[img * P + bm + threadIdx.x], sss[threadIdx.x]);
}

// ---------------- corr GEMM (2-term): scaled corr [b][t][s] + fused tile maxes ----------------
__global__ void __launch_bounds__(256, 2) k_corr() {
    extern __shared__ char smc[];
    __shared__ unsigned su[128], tu[128];
    uint32_t smb = (smem_u32(smc) + 127u) & ~127u;
    int b = blockIdx.z, bm = blockIdx.y * 128, bn = blockIdx.x * 128;  // bm: s, bn: t
    const __half* Ah = g_Sh + ((size_t)b * P + bm) * COUT;
    const __half* Bh = g_Sh + ((size_t)(4 + b) * P + bn) * COUT;
    const __half* Bl = g_Sl + ((size_t)(4 + b) * P + bn) * COUT;
    float acc[2][8][4] = {};
    gemm_ml(smb, Ah, Bh, Bl, COUT, COUT, COUT, acc);

    if (threadIdx.x < 128) { su[threadIdx.x] = 0u; tu[threadIdx.x] = 0u; }
    __syncthreads();

    int lane = threadIdx.x & 31, wid = threadIdx.x >> 5, wm = wid & 3, wn = wid >> 2;
    const float* ssums = g_ssum + b * P;
    const float* ssumt = g_ssum + (4 + b) * P;
    float* C = g_corr + (size_t)b * P * P;
#pragma unroll
    for (int i = 0; i < 2; i++) {
        int sl0 = wm * 32 + i * 16 + (lane >> 2);
        int s0 = bm + sl0;
        float is0 = rsqrtf(ssums[s0] + 1e-6f), is1 = rsqrtf(ssums[s0 + 8] + 1e-6f);
        unsigned ks0 = 0u, ks1 = 0u;
#pragma unroll
        for (int j = 0; j < 8; j++) {
            int tl0 = wn * 64 + j * 8 + 2 * (lane & 3);
            int t0 = bn + tl0;
            float it0 = rsqrtf(ssumt[t0] + 1e-6f), it1 = rsqrtf(ssumt[t0 + 1] + 1e-6f);
            float c00 = acc[i][j][0] * is0 * it0;
            float c01 = acc[i][j][1] * is0 * it1;
            float c10 = acc[i][j][2] * is1 * it0;
            float c11 = acc[i][j][3] * is1 * it1;
            C[(size_t)t0 * P + s0]           = c00;
            C[(size_t)(t0 + 1) * P + s0]     = c01;
            C[(size_t)t0 * P + s0 + 8]       = c10;
            C[(size_t)(t0 + 1) * P + s0 + 8] = c11;
            unsigned k00 = fkey(c00), k01 = fkey(c01), k10 = fkey(c10), k11 = fkey(c11);
            ks0 = max(ks0, max(k00, k01));
            ks1 = max(ks1, max(k10, k11));
            atomicMax(&tu[tl0],     max(k00, k10));
            atomicMax(&tu[tl0 + 1], max(k01, k11));
        }
        atomicMax(&su[sl0], ks0);
        atomicMax(&su[sl0 + 8], ks1);
    }
    __syncthreads();
    if (threadIdx.x < 128) {
        atomicMax(&g_smaxu[b * P + bm + threadIdx.x], su[threadIdx.x]);
        atomicMax(&g_tmaxu[b * P + bn + threadIdx.x], tu[threadIdx.x]);
    }
}

// ---------------- keys -> guarded reciprocals ----------------
__global__ void k_recip() {
    int i = blockIdx.x * 256 + threadIdx.x;
    if (i < NB * P) {
        float v = funkey(g_smaxu[i]); if (v == 0.f) v = 1e-30f;
        g_isx[i] = 1.f / v;
        float w = funkey(g_tmaxu[i]); if (w == 0.f) w = 1e-30f;
        g_itx[i] = 1.f / w;
    }
}

// ---------------- fused filter + resize + softmax + soft-argmax + flow ----------------
__global__ void __launch_bounds__(256) k_flow(float* __restrict__ out) {
    int tx = blockIdx.x, ty = blockIdx.y, b = blockIdx.z;
    int tid = threadIdx.x;
    const float sc = 31.f / 63.f;
    float fy = ty * sc; int y0 = (int)fy; int y1 = min(y0 + 1, 31); float wy = fy - (float)y0;
    float fx = tx * sc; int x0 = (int)fx; int x1 = min(x0 + 1, 31); float wx = fx - (float)x0;
    int t00 = y0 * 32 + x0, t01 = y0 * 32 + x1, t10 = y1 * 32 + x0, t11 = y1 * 32 + x1;
    const float* C = g_corr + (size_t)b * P * P;
    const float* r00 = C + (size_t)t00 * P;
    const float* r01 = C + (size_t)t01 * P;
    const float* r10 = C + (size_t)t10 * P;
    const float* r11 = C + (size_t)t11 * P;
    float ww00 = (1.f - wy) * (1.f - wx) * g_itx[b * P + t00];
    float ww01 = (1.f - wy) * wx         * g_itx[b * P + t01];
    float ww10 = wy * (1.f - wx)         * g_itx[b * P + t10];
    float ww11 = wy * wx                 * g_itx[b * P + t11];
    const float* isx = g_isx + b * P;
    __shared__ float m[P];
    for (int s = tid; s < P; s += 256) {
        float v00 = r00[s], v01 = r01[s], v10 = r10[s], v11 = r11[s];
        float a = ww00 * v00 * v00 * v00 + ww01 * v01 * v01 * v01
                + ww10 * v10 * v10 * v10 + ww11 * v11 * v11 * v11;
        m[s] = a * isx[s];
    }
    __syncthreads();
    float mx = -INFINITY;
    for (int s = tid; s < P; s += 256) mx = fmaxf(mx, m[s]);
    __shared__ float rd[8];
#pragma unroll
    for (int o = 16; o > 0; o >>= 1) mx = fmaxf(mx, __shfl_xor_sync(0xffffffffu, mx, o));
    if ((tid & 31) == 0) rd[tid >> 5] = mx;
    __syncthreads();
    float M = -INFINITY;
#pragma unroll
    for (int i = 0; i < 8; i++) M = fmaxf(M, rd[i]);
    float sum = 0.f, sx = 0.f, sy = 0.f;
    for (int s = tid; s < 4096; s += 256) {
        int i = s >> 6, j = s & 63;
        float gy = i * sc; int yy0 = (int)gy; int yy1 = min(yy0 + 1, 31); float a = gy - (float)yy0;
        float gx = j * sc; int xx0 = (int)gx; int xx1 = min(xx0 + 1, 31); float bq = gx - (float)xx0;
        float v = (1.f - a) * ((1.f - bq) * m[yy0 * 32 + xx0] + bq * m[yy0 * 32 + xx1])
                +        a  * ((1.f - bq) * m[yy1 * 32 + xx0] + bq * m[yy1 * 32 + xx1]);
        float e = __expf((v - M) * 50.f);
        sum += e;
        sx = fmaf(e, -1.f + j * (2.f / 63.f), sx);
        sy = fmaf(e, -1.f + i * (2.f / 63.f), sy);
    }
    __shared__ float rs[8], rx[8], ry[8];
#pragma unroll
    for (int o = 16; o > 0; o >>= 1) {
        sum += __shfl_xor_sync(0xffffffffu, sum, o);
        sx  += __shfl_xor_sync(0xffffffffu, sx,  o);
        sy  += __shfl_xor_sync(0xffffffffu, sy,  o);
    }
    if ((tid & 31) == 0) { rs[tid >> 5] = sum; rx[tid >> 5] = sx; ry[tid >> 5] = sy; }
    __syncthreads();
    if (tid == 0) {
        float S = 0.f, X = 0.f, Y = 0.f;
#pragma unroll
        for (int i = 0; i < 8; i++) { S += rs[i]; X += rx[i]; Y += ry[i]; }
        float gx_ = X / S, gy_ = Y / S;
        out[(size_t)b * 8192 + (size_t)ty * 64 + tx]        = (gx_ + 1.f) * 31.5f - (float)tx;
        out[(size_t)b * 8192 + 4096 + (size_t)ty * 64 + tx] = (gy_ + 1.f) * 31.5f - (float)ty;
    }
}

// ---------------- launch ----------------
extern "C" void kernel_launch(void* const* d_in, const int* in_sizes, int n_in,
                              void* d_out, int out_size) {
    const float* src  = (const float*)d_in[0];
    const float* tgt  = (const float*)d_in[1];
    const float* W    = (const float*)d_in[2];
    const float* bias = (const float*)d_in[3];
    float* out = (float*)d_out;

    cudaFuncSetAttribute(k_conv, cudaFuncAttributeMaxDynamicSharedMemorySize, SMEMB);
    cudaFuncSetAttribute(k_corr, cudaFuncAttributeMaxDynamicSharedMemorySize, SMEMB);

    k_ctx  <<<dim3(8, 32), 256>>>(src, tgt);
    k_xtw  <<<dim3(33, 32, 9), dim3(32, 8)>>>(src, tgt, W);
    k_conv <<<dim3(16, 8, 8), 256, SMEMB>>>(bias);
    k_corr <<<dim3(8, 8, 4), 256, SMEMB>>>();
    k_recip<<<16, 256>>>();
    k_flow <<<dim3(64, 64, 4), 256>>>(out);
}

// round 11
// speedup vs baseline: 1.3172x; 1.3058x over previous
#include <cuda_runtime.h>
#include <cuda_fp16.h>
#include <math.h>
#include <stdint.h>

// ---------------- problem constants ----------------
#define IMGS 8
#define CIN  1024
#define P    1024
#define KC   28
#define KTOT 1052
#define KPAD 1088          // 17 K-stages of 64
#define COUT 2048
#define NB   4

// stage: 256 rows x 128B (rows 0-127: A, rows 128-255: B), K=64 per stage
#define STGB  32768
#define SMEMB (3 * STGB)   // 3-stage ring, 96KB -> 2 CTAs/SM

// ---------------- scratch ----------------
__device__ float  g_ctx [IMGS * KC * P];
__device__ __align__(16) __half g_Wh[COUT * KPAD];
__device__ __align__(16) __half g_Xh[IMGS * P * KPAD];
__device__ __align__(16) __half g_Sh[(size_t)IMGS * P * COUT];
__device__ float  g_ssum[IMGS * P];
__device__ float  g_corr[(size_t)NB * P * P];              // scaled corr, [b][t][s]
__device__ unsigned g_smaxu[NB * P], g_tmaxu[NB * P];      // monotonic float keys
__device__ float  g_isx[NB * P], g_itx[NB * P];

__device__ const int c_dy[28] = {-3,-2,-1,0,1,2,3, -3,-2,-1,0,1,2,3, -3,-2,-1,0,1,2,3, 0,0,0,0,0,0,0};
__device__ const int c_dx[28] = {-3,-2,-1,0,1,2,3,  0, 0, 0,0,0,0,0,  3, 2, 1,0,-1,-2,-3, -3,-2,-1,0,1,2,3};

__device__ __forceinline__ const float* img_ptr(const float* src, const float* tgt, int img) {
    return (img < 4) ? (src + (size_t)img * CIN * P) : (tgt + (size_t)(img - 4) * CIN * P);
}
__device__ __forceinline__ uint32_t smem_u32(const void* p) {
    uint32_t a;
    asm("{ .reg .u64 t; cvta.to.shared.u64 t, %1; cvt.u32.u64 %0, t; }" : "=r"(a) : "l"(p));
    return a;
}
__device__ __forceinline__ void cp16(uint32_t dst, const void* src) {
    asm volatile("cp.async.cg.shared.global [%0], [%1], 16;" :: "r"(dst), "l"(src) : "memory");
}
__device__ __forceinline__ void ldsm4(uint32_t r[4], uint32_t a) {
    asm volatile("ldmatrix.sync.aligned.m8n8.x4.shared.b16 {%0,%1,%2,%3}, [%4];"
        : "=r"(r[0]), "=r"(r[1]), "=r"(r[2]), "=r"(r[3]) : "r"(a));
}
__device__ __forceinline__ void mma16816(float c[4], const uint32_t a[4], const uint32_t b[2]) {
    asm volatile("mma.sync.aligned.m16n8k16.row.col.f32.f16.f16.f32 "
        "{%0,%1,%2,%3},{%4,%5,%6,%7},{%8,%9},{%0,%1,%2,%3};"
        : "+f"(c[0]), "+f"(c[1]), "+f"(c[2]), "+f"(c[3])
        : "r"(a[0]), "r"(a[1]), "r"(a[2]), "r"(a[3]), "r"(b[0]), "r"(b[1]));
}
__device__ __forceinline__ unsigned fkey(float v) {
    unsigned b = __float_as_uint(v);
    return (b & 0x80000000u) ? ~b : (b | 0x80000000u);
}
__device__ __forceinline__ float funkey(unsigned k) {
    unsigned b = (k & 0x80000000u) ? (k & 0x7FFFFFFFu) : ~k;
    return __uint_as_float(b);
}

// ---------------- one 128x128x64 stage of MMA from swizzled smem ----------------
__device__ __forceinline__ void compute_stage(uint32_t bb, const uint32_t aoff[2],
                                              const uint32_t boff[4], float acc[2][8][4])
{
#pragma unroll
    for (int kk = 0; kk < 4; kk++) {
        uint32_t a_h[2][4];
#pragma unroll
        for (int i = 0; i < 2; i++)
            ldsm4(a_h[i], (bb + aoff[i]) ^ (kk << 5));
#pragma unroll
        for (int jj = 0; jj < 4; jj++) {
            uint32_t bh4[4];
            ldsm4(bh4, (bb + boff[jj]) ^ (kk << 5));
#pragma unroll
            for (int i = 0; i < 2; i++) {
                mma16816(acc[i][jj * 2],     a_h[i], bh4 + 0);
                mma16816(acc[i][jj * 2 + 1], a_h[i], bh4 + 2);
            }
        }
    }
}

// ---------------- GEMM mainloop: 3-stage cp.async ring, K=64/stage, swizzled smem ----------------
__device__ __forceinline__ void gemm_ml(uint32_t smb,
    const __half* Ah, const __half* Bh, int lda, int ldb, int K, float acc[2][8][4])
{
    int tid = threadIdx.x, lane = tid & 31, wid = tid >> 5;
    int wm = wid & 3, wn = wid >> 2;
    int rr = tid >> 2;             // 0..63
    int cq = (tid & 3) * 2;        // chunk 0,2,4,6
    uint32_t ro  = (uint32_t)rr * 128;
    uint32_t sw0 = (uint32_t)((cq ^ (rr & 7)) * 16);
    uint32_t sw1 = (uint32_t)(((cq + 1) ^ (rr & 7)) * 16);
    const __half* pA0 = Ah + (size_t)rr * lda + cq * 8;
    const __half* pA1 = Ah + (size_t)(rr + 64) * lda + cq * 8;
    const __half* pB0 = Bh + (size_t)rr * ldb + cq * 8;
    const __half* pB1 = Bh + (size_t)(rr + 64) * ldb + cq * 8;

    uint32_t aoff[2], boff[4];
#pragma unroll
    for (int i = 0; i < 2; i++) {
        int row = wm * 32 + i * 16 + (lane & 15);
        aoff[i] = (uint32_t)row * 128 + (uint32_t)((((lane >> 4) ^ (lane & 7)) & 7) * 16);
    }
#pragma unroll
    for (int jj = 0; jj < 4; jj++) {
        int row = 128 + wn * 64 + jj * 16 + (lane & 7) + ((lane >> 4) & 1) * 8;
        boff[jj] = (uint32_t)row * 128 + (uint32_t)(((((lane >> 3) & 1) ^ (lane & 7)) & 7) * 16);
    }

#define ISSUE(buf, k0) do { \
        uint32_t bb = smb + (uint32_t)(buf) * STGB; \
        cp16(bb + ro + sw0,          pA0 + (k0)); \
        cp16(bb + ro + sw1,          pA0 + (k0) + 8); \
        cp16(bb + ro + 8192 + sw0,   pA1 + (k0)); \
        cp16(bb + ro + 8192 + sw1,   pA1 + (k0) + 8); \
        cp16(bb + ro + 16384 + sw0,  pB0 + (k0)); \
        cp16(bb + ro + 16384 + sw1,  pB0 + (k0) + 8); \
        cp16(bb + ro + 24576 + sw0,  pB1 + (k0)); \
        cp16(bb + ro + 24576 + sw1,  pB1 + (k0) + 8); \
        asm volatile("cp.async.commit_group;" ::: "memory"); \
    } while (0)

    int nst = K / 64;
    ISSUE(0, 0);
    ISSUE(1, 64);
    int buf = 0;
    for (int s = 0; s < nst; s++) {
        if (s + 1 < nst) { asm volatile("cp.async.wait_group 1;" ::: "memory"); }
        else             { asm volatile("cp.async.wait_group 0;" ::: "memory"); }
        __syncthreads();
        int nx = s + 2;
        if (nx < nst) ISSUE(nx % 3, nx * 64);
        compute_stage(smb + (uint32_t)buf * STGB, aoff, boff, acc);
        buf = (buf + 1 == 3) ? 0 : buf + 1;
    }
#undef ISSUE
}

// ---------------- kernel 1: context channels with fused local norms ----------------
__global__ void k_ctx(const float* __restrict__ src, const float* __restrict__ tgt) {
    int img = blockIdx.x, y = blockIdx.y;
    const float* f = img_ptr(src, tgt, img);
    int lane = threadIdx.x & 31, w = threadIdx.x >> 5;
    __shared__ float tile[8][7][32];
    __shared__ float red[28][8][32];
    __shared__ float redn[7][8][32];
    __shared__ float invl[7][32];
    float acc[28];
    float accn[7];
#pragma unroll
    for (int k = 0; k < 28; k++) acc[k] = 0.f;
#pragma unroll
    for (int d = 0; d < 7; d++) accn[d] = 0.f;

    for (int c = w; c < CIN; c += 8) {
#pragma unroll
        for (int dy = 0; dy < 7; dy++) {
            int yy = y + dy - 3;
            float v = (yy >= 0 && yy < 32) ? f[c * P + yy * 32 + lane] : 0.f;
            tile[w][dy][lane] = v;
            accn[dy] = fmaf(v, v, accn[dy]);
        }
        __syncwarp();
        float v0 = tile[w][3][lane];
#pragma unroll
        for (int k = 0; k < 28; k++) {
            int xx = lane + c_dx[k];
            float v = (xx >= 0 && xx < 32) ? tile[w][c_dy[k] + 3][xx] : 0.f;
            acc[k] = fmaf(v0, v, acc[k]);
        }
        __syncwarp();
    }
#pragma unroll
    for (int k = 0; k < 28; k++) red[k][w][lane] = acc[k];
#pragma unroll
    for (int d = 0; d < 7; d++) redn[d][w][lane] = accn[d];
    __syncthreads();

    if (threadIdx.x < 7 * 32) {
        int d = threadIdx.x >> 5, x = threadIdx.x & 31;
        float s = 0.f;
#pragma unroll
        for (int i = 0; i < 8; i++) s += redn[d][i][x];
        invl[d][x] = 1.f / fmaxf(sqrtf(s), 1e-12f);
    }
    __syncthreads();

    for (int idx = threadIdx.x; idx < 28 * 32; idx += 256) {
        int k = idx >> 5, x = idx & 31;
        float s = 0.f;
#pragma unroll
        for (int i = 0; i < 8; i++) s += red[k][i][x];
        int yy = y + c_dy[k], xx = x + c_dx[k];
        float o = 0.f;
        if (yy >= 0 && yy < 32 && xx >= 0 && xx < 32)
            o = s * invl[3][x] * invl[c_dy[k] + 3][xx];
        g_ctx[((size_t)img * KC + k) * P + y * 32 + x] = o;
    }
}

// ---------------- kernel 2: transpose inputs (z<8) / pad W + zero scratch (z==8) ----------------
__global__ void k_xtw(const float* __restrict__ src, const float* __restrict__ tgt,
                      const float* __restrict__ W) {
    int img = blockIdx.z;
    int tid = threadIdx.y * 32 + threadIdx.x;
    if (img == 8) {
        int gid = (blockIdx.y * 34 + blockIdx.x) * 256 + tid;
        if (gid < IMGS * P) g_ssum[gid] = 0.f;
        if (gid < NB * P) { g_smaxu[gid] = 0u; g_tmaxu[gid] = 0u; }
        size_t base = ((size_t)gid) * 8;
        if (base < (size_t)COUT * KPAD) {
#pragma unroll
            for (int u = 0; u < 8; u++) {
                size_t idx = base + u;
                int o = (int)(idx / KPAD);
                int k = (int)(idx - (size_t)o * KPAD);
                float v = (k < KTOT) ? W[(size_t)o * KTOT + k] : 0.f;
                g_Wh[idx] = __float2half_rn(v);
            }
        }
        return;
    }
    int cblk = blockIdx.x, pblk = blockIdx.y;
    const float* f = img_ptr(src, tgt, img);
    __shared__ float tile[32][33];
    int tx = threadIdx.x;
    for (int r = threadIdx.y; r < 32; r += 8) {
        int c = cblk * 32 + r, p = pblk * 32 + tx;
        float v = 0.f;
        if (c < CIN) v = f[(size_t)c * P + p];
        else if (c < KTOT) v = g_ctx[((size_t)img * KC + (c - CIN)) * P + p];
        tile[r][tx] = v;
    }
    __syncthreads();
    for (int r = threadIdx.y; r < 32; r += 8) {
        int p = pblk * 32 + r, c = cblk * 32 + tx;
        g_Xh[((size_t)img * P + p) * KPAD + c] = __float2half_rn(tile[tx][r]);
    }
}

// ---------------- conv GEMM (plain fp16: Xh * Wh) ----------------
__global__ void __launch_bounds__(256, 2) k_conv(const float* __restrict__ bias) {
    extern __shared__ char smc[];
    __shared__ float sss[128];
    uint32_t smb = (smem_u32(smc) + 127u) & ~127u;
    int img = blockIdx.z, bm = blockIdx.y * 128, bn = blockIdx.x * 128;  // bm: p, bn: o
    const __half* Ah = g_Xh + ((size_t)img * P + bm) * KPAD;
    const __half* Bh = g_Wh + (size_t)bn * KPAD;
    float acc[2][8][4] = {};
    gemm_ml(smb, Ah, Bh, KPAD, KPAD, KPAD, acc);

    if (threadIdx.x < 128) sss[threadIdx.x] = 0.f;
    __syncthreads();

    int lane = threadIdx.x & 31, wid = threadIdx.x >> 5, wm = wid & 3, wn = wid >> 2;
    __half* Shp = g_Sh + (size_t)img * P * COUT;
#pragma unroll
    for (int i = 0; i < 2; i++) {
        int pl0 = wm * 32 + i * 16 + (lane >> 2);
        int p0 = bm + pl0;
        float q0 = 0.f, q1 = 0.f;
#pragma unroll
        for (int j = 0; j < 8; j++) {
            int o = bn + wn * 64 + j * 8 + 2 * (lane & 3);
            float2 bb = *(const float2*)(bias + o);
            float a0 = fmaxf(acc[i][j][0] + bb.x, 0.f);
            float a1 = fmaxf(acc[i][j][1] + bb.y, 0.f);
            float a2 = fmaxf(acc[i][j][2] + bb.x, 0.f);
            float a3 = fmaxf(acc[i][j][3] + bb.y, 0.f);
            q0 = fmaf(a0, a0, fmaf(a1, a1, q0));
            q1 = fmaf(a2, a2, fmaf(a3, a3, q1));
            *(__half2*)(Shp + (size_t)p0 * COUT + o)       = __halves2half2(__float2half_rn(a0), __float2half_rn(a1));
            *(__half2*)(Shp + (size_t)(p0 + 8) * COUT + o) = __halves2half2(__float2half_rn(a2), __float2half_rn(a3));
        }
        atomicAdd(&sss[pl0], q0);
        atomicAdd(&sss[pl0 + 8], q1);
    }
    __syncthreads();
    if (threadIdx.x < 128) atomicAdd(&g_ssum[img * P + bm + threadIdx.x], sss[threadIdx.x]);
}

// ---------------- corr GEMM (plain fp16): scaled corr [b][t][s] + fused tile maxes ----------------
__global__ void __launch_bounds__(256, 2) k_corr() {
    extern __shared__ char smc[];
    __shared__ unsigned su[128], tu[128];
    uint32_t smb = (smem_u32(smc) + 127u) & ~127u;
    int b = blockIdx.z, bm = blockIdx.y * 128, bn = blockIdx.x * 128;  // bm: s, bn: t
    const __half* Ah = g_Sh + ((size_t)b * P + bm) * COUT;
    const __half* Bh = g_Sh + ((size_t)(4 + b) * P + bn) * COUT;
    float acc[2][8][4] = {};
    gemm_ml(smb, Ah, Bh, COUT, COUT, COUT, acc);

    if (threadIdx.x < 128) { su[threadIdx.x] = 0u; tu[threadIdx.x] = 0u; }
    __syncthreads();

    int lane = threadIdx.x & 31, wid = threadIdx.x >> 5, wm = wid & 3, wn = wid >> 2;
    const float* ssums = g_ssum + b * P;
    const float* ssumt = g_ssum + (4 + b) * P;
    float* C = g_corr + (size_t)b * P * P;
#pragma unroll
    for (int i = 0; i < 2; i++) {
        int sl0 = wm * 32 + i * 16 + (lane >> 2);
        int s0 = bm + sl0;
        float is0 = rsqrtf(ssums[s0] + 1e-6f), is1 = rsqrtf(ssums[s0 + 8] + 1e-6f);
        unsigned ks0 = 0u, ks1 = 0u;
#pragma unroll
        for (int j = 0; j < 8; j++) {
            int tl0 = wn * 64 + j * 8 + 2 * (lane & 3);
            int t0 = bn + tl0;
            float it0 = rsqrtf(ssumt[t0] + 1e-6f), it1 = rsqrtf(ssumt[t0 + 1] + 1e-6f);
            float c00 = acc[i][j][0] * is0 * it0;
            float c01 = acc[i][j][1] * is0 * it1;
            float c10 = acc[i][j][2] * is1 * it0;
            float c11 = acc[i][j][3] * is1 * it1;
            C[(size_t)t0 * P + s0]           = c00;
            C[(size_t)(t0 + 1) * P + s0]     = c01;
            C[(size_t)t0 * P + s0 + 8]       = c10;
            C[(size_t)(t0 + 1) * P + s0 + 8] = c11;
            unsigned k00 = fkey(c00), k01 = fkey(c01), k10 = fkey(c10), k11 = fkey(c11);
            ks0 = max(ks0, max(k00, k01));
            ks1 = max(ks1, max(k10, k11));
            atomicMax(&tu[tl0],     max(k00, k10));
            atomicMax(&tu[tl0 + 1], max(k01, k11));
        }
        atomicMax(&su[sl0], ks0);
        atomicMax(&su[sl0 + 8], ks1);
    }
    __syncthreads();
    if (threadIdx.x < 128) {
        atomicMax(&g_smaxu[b * P + bm + threadIdx.x], su[threadIdx.x]);
        atomicMax(&g_tmaxu[b * P + bn + threadIdx.x], tu[threadIdx.x]);
    }
}

// ---------------- keys -> guarded reciprocals ----------------
__global__ void k_recip() {
    int i = blockIdx.x * 256 + threadIdx.x;
    if (i < NB * P) {
        float v = funkey(g_smaxu[i]); if (v == 0.f) v = 1e-30f;
        g_isx[i] = 1.f / v;
        float w = funkey(g_tmaxu[i]); if (w == 0.f) w = 1e-30f;
        g_itx[i] = 1.f / w;
    }
}

// ---------------- fused filter + resize + softmax + soft-argmax + flow ----------------
__global__ void __launch_bounds__(256) k_flow(float* __restrict__ out) {
    int tx = blockIdx.x, ty = blockIdx.y, b = blockIdx.z;
    int tid = threadIdx.x;
    const float sc = 31.f / 63.f;
    float fy = ty * sc; int y0 = (int)fy; int y1 = min(y0 + 1, 31); float wy = fy - (float)y0;
    float fx = tx * sc; int x0 = (int)fx; int x1 = min(x0 + 1, 31); float wx = fx - (float)x0;
    int t00 = y0 * 32 + x0, t01 = y0 * 32 + x1, t10 = y1 * 32 + x0, t11 = y1 * 32 + x1;
    const float* C = g_corr + (size_t)b * P * P;
    const float* r00 = C + (size_t)t00 * P;
    const float* r01 = C + (size_t)t01 * P;
    const float* r10 = C + (size_t)t10 * P;
    const float* r11 = C + (size_t)t11 * P;
    float ww00 = (1.f - wy) * (1.f - wx) * g_itx[b * P + t00];
    float ww01 = (1.f - wy) * wx         * g_itx[b * P + t01];
    float ww10 = wy * (1.f - wx)         * g_itx[b * P + t10];
    float ww11 = wy * wx                 * g_itx[b * P + t11];
    const float* isx = g_isx + b * P;
    __shared__ float m[P];
    for (int s = tid; s < P; s += 256) {
        float v00 = r00[s], v01 = r01[s], v10 = r10[s], v11 = r11[s];
        float a = ww00 * v00 * v00 * v00 + ww01 * v01 * v01 * v01
                + ww10 * v10 * v10 * v10 + ww11 * v11 * v11 * v11;
        m[s] = a * isx[s];
    }
    __syncthreads();
    float mx = -INFINITY;
    for (int s = tid; s < P; s += 256) mx = fmaxf(mx, m[s]);
    __shared__ float rd[8];
#pragma unroll
    for (int o = 16; o > 0; o >>= 1) mx = fmaxf(mx, __shfl_xor_sync(0xffffffffu, mx, o));
    if ((tid & 31) == 0) rd[tid >> 5] = mx;
    __syncthreads();
    float M = -INFINITY;
#pragma unroll
    for (int i = 0; i < 8; i++) M = fmaxf(M, rd[i]);
    float sum = 0.f, sx = 0.f, sy = 0.f;
    for (int s = tid; s < 4096; s += 256) {
        int i = s >> 6, j = s & 63;
        float gy = i * sc; int yy0 = (int)gy; int yy1 = min(yy0 + 1, 31); float a = gy - (float)yy0;
        float gx = j * sc; int xx0 = (int)gx; int xx1 = min(xx0 + 1, 31); float bq = gx - (float)xx0;
        float v = (1.f - a) * ((1.f - bq) * m[yy0 * 32 + xx0] + bq * m[yy0 * 32 + xx1])
                +        a  * ((1.f - bq) * m[yy1 * 32 + xx0] + bq * m[yy1 * 32 + xx1]);
        float e = __expf((v - M) * 50.f);
        sum += e;
        sx = fmaf(e, -1.f + j * (2.f / 63.f), sx);
        sy = fmaf(e, -1.f + i * (2.f / 63.f), sy);
    }
    __shared__ float rs[8], rx[8], ry[8];
#pragma unroll
    for (int o = 16; o > 0; o >>= 1) {
        sum += __shfl_xor_sync(0xffffffffu, sum, o);
        sx  += __shfl_xor_sync(0xffffffffu, sx,  o);
        sy  += __shfl_xor_sync(0xffffffffu, sy,  o);
    }
    if ((tid & 31) == 0) { rs[tid >> 5] = sum; rx[tid >> 5] = sx; ry[tid >> 5] = sy; }
    __syncthreads();
    if (tid == 0) {
        float S = 0.f, X = 0.f, Y = 0.f;
#pragma unroll
        for (int i = 0; i < 8; i++) { S += rs[i]; X += rx[i]; Y += ry[i]; }
        float gx_ = X / S, gy_ = Y / S;
        out[(size_t)b * 8192 + (size_t)ty * 64 + tx]        = (gx_ + 1.f) * 31.5f - (float)tx;
        out[(size_t)b * 8192 + 4096 + (size_t)ty * 64 + tx] = (gy_ + 1.f) * 31.5f - (float)ty;
    }
}

// ---------------- launch ----------------
extern "C" void kernel_launch(void* const* d_in, const int* in_sizes, int n_in,
                              void* d_out, int out_size) {
    const float* src  = (const float*)d_in[0];
    const float* tgt  = (const float*)d_in[1];
    const float* W    = (const float*)d_in[2];
    const float* bias = (const float*)d_in[3];
    float* out = (float*)d_out;

    cudaFuncSetAttribute(k_conv, cudaFuncAttributeMaxDynamicSharedMemorySize, SMEMB);
    cudaFuncSetAttribute(k_corr, cudaFuncAttributeMaxDynamicSharedMemorySize, SMEMB);

    k_ctx  <<<dim3(8, 32), 256>>>(src, tgt);
    k_xtw  <<<dim3(34, 32, 9), dim3(32, 8)>>>(src, tgt, W);
    k_conv <<<dim3(16, 8, 8), 256, SMEMB>>>(bias);
    k_corr <<<dim3(8, 8, 4), 256, SMEMB>>>();
    k_recip<<<16, 256>>>();
    k_flow <<<dim3(64, 64, 4), 256>>>(out);
}